// round 1
// baseline (speedup 1.0000x reference)
#include <cuda_runtime.h>
#include <math.h>

#define NATOMS 10000
#define NEDGE  64000
#define BG     128
#define HID    600
#define NG     50
#define NL     6
#define HID4   150   // HID/4

// ------------------------- scratch (static device globals) -------------------
__device__ float g_d  [NEDGE];
__device__ float g_Cc [NEDGE];
__device__ float g_rbf[NEDGE * NG];
__device__ float g_F1 [(size_t)NEDGE * HID];
__device__ float g_W  [(size_t)NEDGE * HID];
__device__ float g_h  [NATOMS * HID];
__device__ float g_xjp[NATOMS * HID];
__device__ float g_agg[NATOMS * HID];
__device__ float g_t1 [NATOMS * HID];
__device__ float g_pool[BG * HID];

// ------------------------- helpers ------------------------------------------
__device__ __forceinline__ float sspf(float x) {
    // softplus(x) - log(2), numerically stable
    float ax = fabsf(x);
    return fmaxf(x, 0.0f) + log1pf(expf(-ax)) - 0.69314718055994531f;
}

// ------------------------- edge geometry ------------------------------------
__global__ void edge_geom_kernel(const float* __restrict__ pos,
                                 const int* __restrict__ src,
                                 const int* __restrict__ dst) {
    int e = blockIdx.x * blockDim.x + threadIdx.x;
    if (e >= NEDGE) return;
    int s = src[e], t = dst[e];
    float dx = pos[s*3+0] - pos[t*3+0];
    float dy = pos[s*3+1] - pos[t*3+1];
    float dz = pos[s*3+2] - pos[t*3+2];
    float d = sqrtf(dx*dx + dy*dy + dz*dz + 1e-12f);
    g_d[e]  = d;
    g_Cc[e] = 0.5f * (cosf(d * 0.31415926535897931f) + 1.0f); // pi/10
}

__global__ void rbf_kernel() {
    int i = blockIdx.x * blockDim.x + threadIdx.x;
    if (i >= NEDGE * NG) return;
    int e = i / NG;
    int g = i - e * NG;
    float off = (float)g * (10.0f / 49.0f);
    float dd  = g_d[e] - off;
    g_rbf[i] = expf(-12.005f * dd * dd);   // -0.5/(10/49)^2 = -12.005 exactly
}

// ------------------------- embedding gather ----------------------------------
__global__ void emb_kernel(const int* __restrict__ z, const float* __restrict__ emb) {
    int i = blockIdx.x * blockDim.x + threadIdx.x;
    if (i >= NATOMS * HID) return;
    int n = i / HID;
    int j = i - n * HID;
    g_h[i] = emb[z[n] * HID + j];
}

// ------------------------- zero ----------------------------------------------
__global__ void zero_kernel(float* __restrict__ p, int n) {
    int i = blockIdx.x * blockDim.x + threadIdx.x;
    if (i < n) p[i] = 0.0f;
}

// ------------------------- generic tiled SGEMM with fused epilogue -----------
// C[M,N] = epilogue( A[M,K] @ Bw[K,N] )
// epilogue: v = acc (+ bias[n]) ; if ssp -> sspf(v) ; if rowscale -> v*=rs[m] ;
//           if addsrc -> v += addsrc[m,n]
#define TBM 128
#define TBN 128
#define TBK 8

__global__ __launch_bounds__(256)
void gemm_ep_kernel(const float* __restrict__ A,
                    const float* __restrict__ Bw,
                    const float* __restrict__ bias,      // [N] or null
                    const float* __restrict__ rowscale,  // [M] or null
                    const float* __restrict__ addsrc,    // [M,N] or null
                    float* __restrict__ C,
                    int M, int N, int K, int do_ssp) {
    __shared__ float As[TBK][TBM];
    __shared__ float Bs[TBK][TBN];
    const int bm = blockIdx.y * TBM;
    const int bn = blockIdx.x * TBN;
    const int tid = threadIdx.x;
    const int tx = tid & 15;            // 0..15 col group
    const int ty = tid >> 4;            // 0..15 row group
    const int row0 = ty * 8;
    const int col0 = tx * 8;

    // load mapping (4 elems per thread per tile)
    const int a_m  = (tid * 4) >> 3;    // 0..127
    const int a_k0 = (tid * 4) & 7;     // 0 or 4
    const int b_k  = (tid * 4) >> 7;    // 0..7
    const int b_n0 = (tid * 4) & 127;

    float acc[8][8];
    #pragma unroll
    for (int i = 0; i < 8; i++)
        #pragma unroll
        for (int j = 0; j < 8; j++) acc[i][j] = 0.0f;

    for (int k0 = 0; k0 < K; k0 += TBK) {
        // ---- load A tile (transposed into As[k][m]) ----
        {
            int gm = bm + a_m;
            bool mok = (gm < M);
            const float* ap = A + (size_t)gm * K;
            #pragma unroll
            for (int i = 0; i < 4; i++) {
                int gk = k0 + a_k0 + i;
                As[a_k0 + i][a_m] = (mok && gk < K) ? ap[gk] : 0.0f;
            }
        }
        // ---- load B tile ----
        {
            int gk = k0 + b_k;
            bool kok = (gk < K);
            const float* bp = Bw + (size_t)gk * N + bn;
            #pragma unroll
            for (int i = 0; i < 4; i++) {
                int gn = bn + b_n0 + i;
                Bs[b_k][b_n0 + i] = (kok && gn < N) ? bp[b_n0 + i] : 0.0f;
            }
        }
        __syncthreads();

        #pragma unroll
        for (int kk = 0; kk < TBK; kk++) {
            float4 a0 = *(const float4*)&As[kk][row0];
            float4 a1 = *(const float4*)&As[kk][row0 + 4];
            float4 b0 = *(const float4*)&Bs[kk][col0];
            float4 b1 = *(const float4*)&Bs[kk][col0 + 4];
            float a[8] = {a0.x, a0.y, a0.z, a0.w, a1.x, a1.y, a1.z, a1.w};
            float b[8] = {b0.x, b0.y, b0.z, b0.w, b1.x, b1.y, b1.z, b1.w};
            #pragma unroll
            for (int i = 0; i < 8; i++)
                #pragma unroll
                for (int j = 0; j < 8; j++)
                    acc[i][j] = fmaf(a[i], b[j], acc[i][j]);
        }
        __syncthreads();
    }

    // ---- epilogue ----
    #pragma unroll
    for (int i = 0; i < 8; i++) {
        int gm = bm + row0 + i;
        if (gm >= M) continue;
        float rs = rowscale ? rowscale[gm] : 1.0f;
        #pragma unroll
        for (int j = 0; j < 8; j++) {
            int gn = bn + col0 + j;
            if (gn >= N) continue;
            float v = acc[i][j];
            if (bias) v += bias[gn];
            if (do_ssp) v = sspf(v);
            if (rowscale) v *= rs;
            if (addsrc) v += addsrc[(size_t)gm * N + gn];
            C[(size_t)gm * N + gn] = v;
        }
    }
}

// ------------------------- CFConv scatter ------------------------------------
// agg[dst[e], :] += xjp[src[e], :] * W[e, :]   (vectorized float4 reductions)
__global__ void scatter_kernel(const int* __restrict__ src,
                               const int* __restrict__ dst) {
    int i = blockIdx.x * blockDim.x + threadIdx.x;
    if (i >= NEDGE * HID4) return;
    int e = i / HID4;
    int j = i - e * HID4;
    int s = src[e], d = dst[e];
    const float4* xp = (const float4*)g_xjp;
    const float4* wp = (const float4*)g_W;
    float4 x = xp[(size_t)s * HID4 + j];
    float4 w = wp[(size_t)e * HID4 + j];
    float4 v;
    v.x = x.x * w.x; v.y = x.y * w.y; v.z = x.z * w.z; v.w = x.w * w.w;
    float* a = g_agg + ((size_t)d * HID + j * 4);
    asm volatile("red.global.add.v4.f32 [%0], {%1,%2,%3,%4};"
                 :: "l"(a), "f"(v.x), "f"(v.y), "f"(v.z), "f"(v.w) : "memory");
}

// ------------------------- segment-mean pool (batch is sorted) ---------------
__global__ void pool_kernel(const int* __restrict__ batch) {
    int b = blockIdx.x;
    int t = threadIdx.x;
    // binary search for [start, end) of graph b in sorted batch array
    int lo = 0, hi = NATOMS;
    while (lo < hi) { int mid = (lo + hi) >> 1; if (batch[mid] < b) lo = mid + 1; else hi = mid; }
    int start = lo;
    lo = start; hi = NATOMS;
    while (lo < hi) { int mid = (lo + hi) >> 1; if (batch[mid] <= b) lo = mid + 1; else hi = mid; }
    int end = lo;
    int cnt = end - start;
    float inv = cnt > 0 ? 1.0f / (float)cnt : 0.0f;
    if (t < HID) {
        float s = 0.0f;
        for (int n = start; n < end; n++) s += g_h[n * HID + t];
        g_pool[b * HID + t] = s * inv;
    }
}

// ------------------------- host orchestration --------------------------------
static inline void launch_gemm(const float* A, const float* Bw, const float* bias,
                               const float* rowscale, const float* addsrc,
                               float* C, int M, int N, int K, int do_ssp) {
    dim3 grid((N + TBN - 1) / TBN, (M + TBM - 1) / TBM);
    gemm_ep_kernel<<<grid, 256>>>(A, Bw, bias, rowscale, addsrc, C, M, N, K, do_ssp);
}

extern "C" void kernel_launch(void* const* d_in, const int* in_sizes, int n_in,
                              void* d_out, int out_size) {
    const int*   z     = (const int*)  d_in[0];
    const float* pos   = (const float*)d_in[1];
    const int*   batch = (const int*)  d_in[2];
    const int*   ei    = (const int*)  d_in[3];
    const float* emb   = (const float*)d_in[4];
    const float* w1    = (const float*)d_in[5];
    const float* b1    = (const float*)d_in[6];
    const float* w2    = (const float*)d_in[7];
    const float* b2    = (const float*)d_in[8];
    const float* l1w   = (const float*)d_in[9];
    const float* l2w   = (const float*)d_in[10];
    const float* l2b   = (const float*)d_in[11];
    const float* ilw   = (const float*)d_in[12];
    const float* ilb   = (const float*)d_in[13];
    const float* pw    = (const float*)d_in[14];
    const float* pb    = (const float*)d_in[15];
    (void)in_sizes; (void)n_in; (void)out_size;

    const int* src = ei;
    const int* dst = ei + NEDGE;

    float *pd, *pCc, *prbf, *pF1, *pW, *ph, *pxjp, *pagg, *pt1, *ppool;
    cudaGetSymbolAddress((void**)&pd,    g_d);
    cudaGetSymbolAddress((void**)&pCc,   g_Cc);
    cudaGetSymbolAddress((void**)&prbf,  g_rbf);
    cudaGetSymbolAddress((void**)&pF1,   g_F1);
    cudaGetSymbolAddress((void**)&pW,    g_W);
    cudaGetSymbolAddress((void**)&ph,    g_h);
    cudaGetSymbolAddress((void**)&pxjp,  g_xjp);
    cudaGetSymbolAddress((void**)&pagg,  g_agg);
    cudaGetSymbolAddress((void**)&pt1,   g_t1);
    cudaGetSymbolAddress((void**)&ppool, g_pool);
    (void)pd;

    // edge geometry + RBF + embedding init
    edge_geom_kernel<<<(NEDGE + 255) / 256, 256>>>(pos, src, dst);
    rbf_kernel<<<(NEDGE * NG + 255) / 256, 256>>>();
    emb_kernel<<<(NATOMS * HID + 255) / 256, 256>>>(z, emb);

    for (int k = 0; k < NL; k++) {
        const float* w1k  = w1  + (size_t)k * NG * HID;
        const float* b1k  = b1  + (size_t)k * HID;
        const float* w2k  = w2  + (size_t)k * HID * HID;
        const float* b2k  = b2  + (size_t)k * HID;
        const float* l1wk = l1w + (size_t)k * HID * HID;
        const float* l2wk = l2w + (size_t)k * HID * HID;
        const float* l2bk = l2b + (size_t)k * HID;
        const float* ilwk = ilw + (size_t)k * HID * HID;
        const float* ilbk = ilb + (size_t)k * HID;

        // F1 = ssp(rbf @ w1 + b1)                       [E,H]
        launch_gemm(prbf, w1k, b1k, nullptr, nullptr, pF1, NEDGE, HID, NG, 1);
        // W = (F1 @ w2 + b2) * C                        [E,H]
        launch_gemm(pF1, w2k, b2k, pCc, nullptr, pW, NEDGE, HID, HID, 0);
        // xjp = h @ lin1                                [N,H]
        launch_gemm(ph, l1wk, nullptr, nullptr, nullptr, pxjp, NATOMS, HID, HID, 0);
        // agg = scatter_add(xjp[src] * W  -> dst)       [N,H]
        zero_kernel<<<(NATOMS * HID + 255) / 256, 256>>>(pagg, NATOMS * HID);
        scatter_kernel<<<(NEDGE * HID4 + 255) / 256, 256>>>(src, dst);
        // t1 = ssp(agg @ lin2 + lin2_b)                 [N,H]
        launch_gemm(pagg, l2wk, l2bk, nullptr, nullptr, pt1, NATOMS, HID, HID, 1);
        // h = h + t1 @ int_lin + int_b                  [N,H]  (residual fused)
        launch_gemm(pt1, ilwk, ilbk, nullptr, ph, ph, NATOMS, HID, HID, 0);
    }

    // segment-mean pool over sorted batch, then final projection into d_out
    pool_kernel<<<BG, 640>>>(batch);
    launch_gemm(ppool, pw, pb, nullptr, nullptr, (float*)d_out, BG, HID, HID, 0);
}

// round 10
// speedup vs baseline: 3.4178x; 3.4178x over previous
#include <cuda_runtime.h>
#include <cuda_bf16.h>
#include <stdint.h>
#include <math.h>

#define NATOMS 10000
#define NEDGE  64000
#define BG     128
#define HID    600
#define NG     50
#define NL     6
#define HID4   150     // HID/4
#define KP_H   608     // HID padded to 16
#define KP_G   64      // NG padded to 16

// ------------------------- scratch (static device globals) -------------------
__device__ float g_d  [NEDGE];
__device__ float g_Cc [NEDGE];
__device__ float g_rbf[NEDGE * NG];
__device__ float g_F1 [(size_t)NEDGE * HID];
__device__ float g_W  [(size_t)NEDGE * HID];
__device__ float g_h  [NATOMS * HID];
__device__ float g_xjp[NATOMS * HID];
__device__ float g_agg[NATOMS * HID];
__device__ float g_t1 [NATOMS * HID];
__device__ float g_pool[BG * HID];

// tf32-rounded transposed weights (stored as f32): layout [N][Kpad]
__device__ float g_w1t [NL * HID * KP_G];
__device__ float g_w2t [NL * HID * KP_H];
__device__ float g_l1t [NL * HID * KP_H];
__device__ float g_l2t [NL * HID * KP_H];
__device__ float g_ilt [NL * HID * KP_H];
__device__ float g_pwt [HID * KP_H];

// ------------------------- helpers ------------------------------------------
__device__ __forceinline__ float sspf(float x) {
    float ax = fabsf(x);
    return fmaxf(x, 0.0f) + log1pf(expf(-ax)) - 0.69314718055994531f;
}

__device__ __forceinline__ float to_tf32(float x) {
    float r;
    asm("cvt.rna.tf32.f32 %0, %1;" : "=f"(r) : "f"(x));
    return r;
}

// ------------------------- edge geometry / rbf / emb -------------------------
__global__ void edge_geom_kernel(const float* __restrict__ pos,
                                 const int* __restrict__ src,
                                 const int* __restrict__ dst) {
    int e = blockIdx.x * blockDim.x + threadIdx.x;
    if (e >= NEDGE) return;
    int s = src[e], t = dst[e];
    float dx = pos[s*3+0] - pos[t*3+0];
    float dy = pos[s*3+1] - pos[t*3+1];
    float dz = pos[s*3+2] - pos[t*3+2];
    float d = sqrtf(dx*dx + dy*dy + dz*dz + 1e-12f);
    g_d[e]  = d;
    g_Cc[e] = 0.5f * (cosf(d * 0.31415926535897931f) + 1.0f);
}

__global__ void rbf_kernel() {
    int i = blockIdx.x * blockDim.x + threadIdx.x;
    if (i >= NEDGE * NG) return;
    int e = i / NG;
    int g = i - e * NG;
    float off = (float)g * (10.0f / 49.0f);
    float dd  = g_d[e] - off;
    g_rbf[i] = expf(-12.005f * dd * dd);
}

__global__ void emb_kernel(const int* __restrict__ z, const float* __restrict__ emb) {
    int i = blockIdx.x * blockDim.x + threadIdx.x;
    if (i >= NATOMS * HID) return;
    int n = i / HID;
    int j = i - n * HID;
    g_h[i] = emb[z[n] * HID + j];
}

__global__ void zero_kernel(float* __restrict__ p, int n) {
    int i = blockIdx.x * blockDim.x + threadIdx.x;
    if (i < n) p[i] = 0.0f;
}

// ------------------------- weight transpose + tf32 round ---------------------
// out[n*Kpad + k] = tf32(in[k*N + n]), zero for k >= K
__global__ void convt_kernel(const float* __restrict__ in, float* __restrict__ out,
                             int K, int N, int Kpad) {
    __shared__ float tile[32][33];
    int kb = blockIdx.x * 32, nb = blockIdx.y * 32;
    int tx = threadIdx.x, ty = threadIdx.y;
    #pragma unroll
    for (int i = ty; i < 32; i += 8) {
        int k = kb + i, n = nb + tx;
        tile[i][tx] = (k < K && n < N) ? in[(size_t)k * N + n] : 0.0f;
    }
    __syncthreads();
    #pragma unroll
    for (int i = ty; i < 32; i += 8) {
        int n = nb + i, k = kb + tx;
        if (n < N && k < Kpad) out[(size_t)n * Kpad + k] = to_tf32(tile[tx][i]);
    }
}

// ------------------------- tf32 tensor-core GEMM with fused epilogue ---------
// C[M,N] = ep( A[M,K](fp32) @ Bt[N,Kpad](tf32-rounded f32, transposed) )
// CTA 128x128x16, 8 warps (2x4), warp tile 64x32, mma.m16n8k8 tf32, fp32 acc.
#define TBM 128
#define TBN 128
#define TBK 16
#define SA  20   // smem row stride in f32 (conflict-free)
#define SB  20

__global__ __launch_bounds__(256, 2)
void gemm_tc_kernel(const float* __restrict__ A,
                    const float* __restrict__ Bt,
                    const float* __restrict__ bias,
                    const float* __restrict__ rowscale,
                    const float* __restrict__ addsrc,
                    float* __restrict__ C,
                    int M, int N, int K, int Kpad, int do_ssp) {
    __shared__ __align__(16) float As[2][TBM * SA];
    __shared__ __align__(16) float Bs[2][TBN * SB];

    const int bm = blockIdx.y * TBM;
    const int bn = blockIdx.x * TBN;
    const int tid  = threadIdx.x;
    const int lane = tid & 31;
    const int warp = tid >> 5;
    const int wm0 = (warp >> 2) * 64;   // 2 warp rows
    const int wn0 = (warp & 3) * 32;    // 4 warp cols
    const int gid = lane >> 2;          // 0..7
    const int lk  = lane & 3;           // 0..3

    // staging mapping: row = tid>>1 (0..127), col half = (tid&1)*8
    const int srow = tid >> 1;
    const int scol = (tid & 1) * 8;

    // A rows are 16B-aligned only when K is a multiple of 4 (row byte stride K*4)
    const bool a_vec_ok = ((K & 3) == 0);

    float acc[4][4][4];
    #pragma unroll
    for (int i = 0; i < 4; i++)
        #pragma unroll
        for (int j = 0; j < 4; j++)
            #pragma unroll
            for (int c = 0; c < 4; c++) acc[i][j][c] = 0.0f;

    const int nsteps = Kpad / TBK;

    float aS[8], bS[8];

    auto loadA = [&](int k0) {
        int gm = bm + srow;
        int kb = k0 + scol;
        if (a_vec_ok && gm < M && kb + 7 < K) {
            const float4* ap = (const float4*)(A + (size_t)gm * K + kb);
            float4 v0 = ap[0], v1 = ap[1];
            aS[0] = v0.x; aS[1] = v0.y; aS[2] = v0.z; aS[3] = v0.w;
            aS[4] = v1.x; aS[5] = v1.y; aS[6] = v1.z; aS[7] = v1.w;
        } else {
            const float* ap = A + (size_t)gm * K;
            #pragma unroll
            for (int i = 0; i < 8; i++)
                aS[i] = (gm < M && kb + i < K) ? ap[kb + i] : 0.0f;
        }
        #pragma unroll
        for (int i = 0; i < 8; i++) aS[i] = to_tf32(aS[i]);
    };
    auto loadB = [&](int k0) {
        int gn = bn + srow;
        if (gn < N) {
            const float4* bp = (const float4*)(Bt + (size_t)gn * Kpad + k0 + scol);
            float4 v0 = bp[0], v1 = bp[1];
            bS[0] = v0.x; bS[1] = v0.y; bS[2] = v0.z; bS[3] = v0.w;
            bS[4] = v1.x; bS[5] = v1.y; bS[6] = v1.z; bS[7] = v1.w;
        } else {
            #pragma unroll
            for (int i = 0; i < 8; i++) bS[i] = 0.0f;
        }
    };
    auto stsA = [&](int buf) {
        float* p = &As[buf][srow * SA + scol];
        *(float4*)p       = make_float4(aS[0], aS[1], aS[2], aS[3]);
        *(float4*)(p + 4) = make_float4(aS[4], aS[5], aS[6], aS[7]);
    };
    auto stsB = [&](int buf) {
        float* p = &Bs[buf][srow * SB + scol];
        *(float4*)p       = make_float4(bS[0], bS[1], bS[2], bS[3]);
        *(float4*)(p + 4) = make_float4(bS[4], bS[5], bS[6], bS[7]);
    };

    loadA(0); loadB(0);
    stsA(0); stsB(0);
    __syncthreads();

    for (int s = 0; s < nsteps; s++) {
        if (s + 1 < nsteps) { loadA((s + 1) * TBK); loadB((s + 1) * TBK); }

        const float* as = As[s & 1];
        const float* bs = Bs[s & 1];
        #pragma unroll
        for (int ks = 0; ks < 2; ks++) {
            int kof = ks * 8 + lk;
            unsigned int af[4][4], bf[4][2];
            #pragma unroll
            for (int mt = 0; mt < 4; mt++) {
                int r = wm0 + mt * 16 + gid;
                af[mt][0] = __float_as_uint(as[r * SA + kof]);
                af[mt][1] = __float_as_uint(as[(r + 8) * SA + kof]);
                af[mt][2] = __float_as_uint(as[r * SA + kof + 4]);
                af[mt][3] = __float_as_uint(as[(r + 8) * SA + kof + 4]);
            }
            #pragma unroll
            for (int nt = 0; nt < 4; nt++) {
                int c = wn0 + nt * 8 + gid;
                bf[nt][0] = __float_as_uint(bs[c * SB + kof]);
                bf[nt][1] = __float_as_uint(bs[c * SB + kof + 4]);
            }
            #pragma unroll
            for (int mt = 0; mt < 4; mt++)
                #pragma unroll
                for (int nt = 0; nt < 4; nt++) {
                    asm volatile(
                        "mma.sync.aligned.m16n8k8.row.col.f32.tf32.tf32.f32 "
                        "{%0,%1,%2,%3}, {%4,%5,%6,%7}, {%8,%9}, {%0,%1,%2,%3};"
                        : "+f"(acc[mt][nt][0]), "+f"(acc[mt][nt][1]),
                          "+f"(acc[mt][nt][2]), "+f"(acc[mt][nt][3])
                        : "r"(af[mt][0]), "r"(af[mt][1]), "r"(af[mt][2]), "r"(af[mt][3]),
                          "r"(bf[nt][0]), "r"(bf[nt][1]));
                }
        }
        if (s + 1 < nsteps) {
            __syncthreads();
            stsA((s + 1) & 1); stsB((s + 1) & 1);
            __syncthreads();
        }
    }

    // ---- epilogue ----  (C frag: row = gid (+8), col = lk*2 (+1))
    #pragma unroll
    for (int mt = 0; mt < 4; mt++) {
        #pragma unroll
        for (int rr = 0; rr < 2; rr++) {
            int gm = bm + wm0 + mt * 16 + gid + rr * 8;
            if (gm >= M) continue;
            float rs = rowscale ? rowscale[gm] : 1.0f;
            #pragma unroll
            for (int nt = 0; nt < 4; nt++) {
                #pragma unroll
                for (int cc = 0; cc < 2; cc++) {
                    int gn = bn + wn0 + nt * 8 + lk * 2 + cc;
                    if (gn >= N) continue;
                    float v = acc[mt][nt][rr * 2 + cc];
                    if (bias) v += bias[gn];
                    if (do_ssp) v = sspf(v);
                    if (rowscale) v *= rs;
                    if (addsrc) v += addsrc[(size_t)gm * N + gn];
                    C[(size_t)gm * N + gn] = v;
                }
            }
        }
    }
}

// ------------------------- CFConv scatter ------------------------------------
__global__ void scatter_kernel(const int* __restrict__ src,
                               const int* __restrict__ dst) {
    int i = blockIdx.x * blockDim.x + threadIdx.x;
    if (i >= NEDGE * HID4) return;
    int e = i / HID4;
    int j = i - e * HID4;
    int s = src[e], d = dst[e];
    const float4* xp = (const float4*)g_xjp;
    const float4* wp = (const float4*)g_W;
    float4 x = xp[(size_t)s * HID4 + j];
    float4 w = wp[(size_t)e * HID4 + j];
    float4 v;
    v.x = x.x * w.x; v.y = x.y * w.y; v.z = x.z * w.z; v.w = x.w * w.w;
    float* a = g_agg + ((size_t)d * HID + j * 4);
    asm volatile("red.global.add.v4.f32 [%0], {%1,%2,%3,%4};"
                 :: "l"(a), "f"(v.x), "f"(v.y), "f"(v.z), "f"(v.w) : "memory");
}

// ------------------------- segment-mean pool ---------------------------------
__global__ void pool_kernel(const int* __restrict__ batch) {
    int b = blockIdx.x;
    int t = threadIdx.x;
    int lo = 0, hi = NATOMS;
    while (lo < hi) { int mid = (lo + hi) >> 1; if (batch[mid] < b) lo = mid + 1; else hi = mid; }
    int start = lo;
    lo = start; hi = NATOMS;
    while (lo < hi) { int mid = (lo + hi) >> 1; if (batch[mid] <= b) lo = mid + 1; else hi = mid; }
    int end = lo;
    int cnt = end - start;
    float inv = cnt > 0 ? 1.0f / (float)cnt : 0.0f;
    if (t < HID) {
        float s = 0.0f;
        for (int n = start; n < end; n++) s += g_h[n * HID + t];
        g_pool[b * HID + t] = s * inv;
    }
}

// ------------------------- host orchestration --------------------------------
static inline void launch_gemm(const float* A, const float* Bt, const float* bias,
                               const float* rowscale, const float* addsrc,
                               float* C, int M, int N, int K, int Kpad, int do_ssp) {
    dim3 grid((N + TBN - 1) / TBN, (M + TBM - 1) / TBM);
    gemm_tc_kernel<<<grid, 256>>>(A, Bt, bias, rowscale, addsrc, C, M, N, K, Kpad, do_ssp);
}

static inline void launch_convt(const float* in, float* out, int K, int N, int Kpad) {
    dim3 grid((Kpad + 31) / 32, (N + 31) / 32);
    convt_kernel<<<grid, dim3(32, 8)>>>(in, out, K, N, Kpad);
}

extern "C" void kernel_launch(void* const* d_in, const int* in_sizes, int n_in,
                              void* d_out, int out_size) {
    const int*   z     = (const int*)  d_in[0];
    const float* pos   = (const float*)d_in[1];
    const int*   batch = (const int*)  d_in[2];
    const int*   ei    = (const int*)  d_in[3];
    const float* emb   = (const float*)d_in[4];
    const float* w1    = (const float*)d_in[5];
    const float* b1    = (const float*)d_in[6];
    const float* w2    = (const float*)d_in[7];
    const float* b2    = (const float*)d_in[8];
    const float* l1w   = (const float*)d_in[9];
    const float* l2w   = (const float*)d_in[10];
    const float* l2b   = (const float*)d_in[11];
    const float* ilw   = (const float*)d_in[12];
    const float* ilb   = (const float*)d_in[13];
    const float* pw    = (const float*)d_in[14];
    const float* pb    = (const float*)d_in[15];
    (void)in_sizes; (void)n_in; (void)out_size;

    const int* src = ei;
    const int* dst = ei + NEDGE;

    float *prbf, *pF1, *pW, *ph, *pxjp, *pagg, *pt1, *ppool, *pCc;
    float *pw1t, *pw2t, *pl1t, *pl2t, *pilt, *ppwt;
    cudaGetSymbolAddress((void**)&pCc,   g_Cc);
    cudaGetSymbolAddress((void**)&prbf,  g_rbf);
    cudaGetSymbolAddress((void**)&pF1,   g_F1);
    cudaGetSymbolAddress((void**)&pW,    g_W);
    cudaGetSymbolAddress((void**)&ph,    g_h);
    cudaGetSymbolAddress((void**)&pxjp,  g_xjp);
    cudaGetSymbolAddress((void**)&pagg,  g_agg);
    cudaGetSymbolAddress((void**)&pt1,   g_t1);
    cudaGetSymbolAddress((void**)&ppool, g_pool);
    cudaGetSymbolAddress((void**)&pw1t,  g_w1t);
    cudaGetSymbolAddress((void**)&pw2t,  g_w2t);
    cudaGetSymbolAddress((void**)&pl1t,  g_l1t);
    cudaGetSymbolAddress((void**)&pl2t,  g_l2t);
    cudaGetSymbolAddress((void**)&pilt,  g_ilt);
    cudaGetSymbolAddress((void**)&ppwt,  g_pwt);

    // weight transpose + tf32 rounding (per launch; cheap)
    for (int k = 0; k < NL; k++) {
        launch_convt(w1  + (size_t)k * NG  * HID, pw1t + (size_t)k * HID * KP_G, NG,  HID, KP_G);
        launch_convt(w2  + (size_t)k * HID * HID, pw2t + (size_t)k * HID * KP_H, HID, HID, KP_H);
        launch_convt(l1w + (size_t)k * HID * HID, pl1t + (size_t)k * HID * KP_H, HID, HID, KP_H);
        launch_convt(l2w + (size_t)k * HID * HID, pl2t + (size_t)k * HID * KP_H, HID, HID, KP_H);
        launch_convt(ilw + (size_t)k * HID * HID, pilt + (size_t)k * HID * KP_H, HID, HID, KP_H);
    }
    launch_convt(pw, ppwt, HID, HID, KP_H);

    // edge geometry + RBF + embedding init
    edge_geom_kernel<<<(NEDGE + 255) / 256, 256>>>(pos, src, dst);
    rbf_kernel<<<(NEDGE * NG + 255) / 256, 256>>>();
    emb_kernel<<<(NATOMS * HID + 255) / 256, 256>>>(z, emb);

    for (int k = 0; k < NL; k++) {
        const float* b1k  = b1  + (size_t)k * HID;
        const float* b2k  = b2  + (size_t)k * HID;
        const float* l2bk = l2b + (size_t)k * HID;
        const float* ilbk = ilb + (size_t)k * HID;
        const float* w1tk = pw1t + (size_t)k * HID * KP_G;
        const float* w2tk = pw2t + (size_t)k * HID * KP_H;
        const float* l1tk = pl1t + (size_t)k * HID * KP_H;
        const float* l2tk = pl2t + (size_t)k * HID * KP_H;
        const float* iltk = pilt + (size_t)k * HID * KP_H;

        // F1 = ssp(rbf @ w1 + b1)                       [E,H]
        launch_gemm(prbf, w1tk, b1k, nullptr, nullptr, pF1, NEDGE, HID, NG, KP_G, 1);
        // W = (F1 @ w2 + b2) * C                        [E,H]
        launch_gemm(pF1, w2tk, b2k, pCc, nullptr, pW, NEDGE, HID, HID, KP_H, 0);
        // xjp = h @ lin1                                [N,H]
        launch_gemm(ph, l1tk, nullptr, nullptr, nullptr, pxjp, NATOMS, HID, HID, KP_H, 0);
        // agg = scatter_add(xjp[src] * W -> dst)        [N,H]
        zero_kernel<<<(NATOMS * HID + 255) / 256, 256>>>(pagg, NATOMS * HID);
        scatter_kernel<<<(NEDGE * HID4 + 255) / 256, 256>>>(src, dst);
        // t1 = ssp(agg @ lin2 + lin2_b)                 [N,H]
        launch_gemm(pagg, l2tk, l2bk, nullptr, nullptr, pt1, NATOMS, HID, HID, KP_H, 1);
        // h = h + t1 @ int_lin + int_b                  [N,H]
        launch_gemm(pt1, iltk, ilbk, nullptr, ph, ph, NATOMS, HID, HID, KP_H, 0);
    }

    // segment-mean pool, final projection
    pool_kernel<<<BG, 640>>>(batch);
    launch_gemm(ppool, ppwt, pb, nullptr, nullptr, (float*)d_out, BG, HID, HID, KP_H, 0);
}

// round 11
// speedup vs baseline: 7.0325x; 2.0576x over previous
#include <cuda_runtime.h>
#include <cuda_bf16.h>
#include <stdint.h>
#include <math.h>

#define NATOMS 10000
#define NEDGE  64000
#define BG     128
#define HID    600
#define NG     50
#define NL     6
#define HID4   150     // HID/4
#define KP_H   608     // HID padded to 16
#define KP_G   64      // NG padded to 16
#define TAB    4096    // W(d) table resolution
#define DMAX   8.6603f // > sqrt(75) = max possible distance
#define TDELTA (DMAX / (TAB - 1))

// ------------------------- scratch (static device globals) -------------------
__device__ int   g_ei0[NEDGE];          // table index per edge
__device__ float g_efr[NEDGE];          // interpolation fraction per edge
__device__ float g_rbftab[TAB * KP_G];  // rbf at table points (padded cols)
__device__ float g_Ctab  [TAB];         // cosine cutoff at table points
__device__ float g_F1tab [TAB * HID];
__device__ float g_Wtab  [TAB * HID];
__device__ float g_h  [NATOMS * HID];
__device__ float g_xjp[NATOMS * HID];
__device__ float g_agg[NATOMS * HID];
__device__ float g_t1 [NATOMS * HID];
__device__ float g_pool[BG * HID];

// tf32-rounded transposed weights (stored as f32): layout [N][Kpad]
__device__ float g_w1t [NL * HID * KP_G];
__device__ float g_w2t [NL * HID * KP_H];
__device__ float g_l1t [NL * HID * KP_H];
__device__ float g_l2t [NL * HID * KP_H];
__device__ float g_ilt [NL * HID * KP_H];
__device__ float g_pwt [HID * KP_H];

// ------------------------- helpers ------------------------------------------
__device__ __forceinline__ float sspf(float x) {
    float ax = fabsf(x);
    return fmaxf(x, 0.0f) + log1pf(expf(-ax)) - 0.69314718055994531f;
}

__device__ __forceinline__ float to_tf32(float x) {
    float r;
    asm("cvt.rna.tf32.f32 %0, %1;" : "=f"(r) : "f"(x));
    return r;
}

// ------------------------- edge geometry -> table coords ---------------------
__global__ void edge_geom_kernel(const float* __restrict__ pos,
                                 const int* __restrict__ src,
                                 const int* __restrict__ dst) {
    int e = blockIdx.x * blockDim.x + threadIdx.x;
    if (e >= NEDGE) return;
    int s = src[e], t = dst[e];
    float dx = pos[s*3+0] - pos[t*3+0];
    float dy = pos[s*3+1] - pos[t*3+1];
    float dz = pos[s*3+2] - pos[t*3+2];
    float d = sqrtf(dx*dx + dy*dy + dz*dz + 1e-12f);
    float tt = d * (1.0f / TDELTA);
    int i0 = (int)tt;
    if (i0 > TAB - 2) i0 = TAB - 2;
    g_ei0[e] = i0;
    g_efr[e] = tt - (float)i0;
}

// ------------------------- rbf + cutoff table --------------------------------
__global__ void rbftab_kernel() {
    int i = blockIdx.x * blockDim.x + threadIdx.x;
    if (i >= TAB * KP_G) return;
    int r = i / KP_G;
    int g = i - r * KP_G;
    float d = (float)r * TDELTA;
    float v = 0.0f;
    if (g < NG) {
        float off = (float)g * (10.0f / 49.0f);
        float dd  = d - off;
        v = expf(-12.005f * dd * dd);
    }
    g_rbftab[i] = v;
    if (g == 0)
        g_Ctab[r] = 0.5f * (cosf(d * 0.31415926535897931f) + 1.0f);
}

__global__ void emb_kernel(const int* __restrict__ z, const float* __restrict__ emb) {
    int i = blockIdx.x * blockDim.x + threadIdx.x;
    if (i >= NATOMS * HID) return;
    int n = i / HID;
    int j = i - n * HID;
    g_h[i] = emb[z[n] * HID + j];
}

__global__ void zero_kernel(float* __restrict__ p, int n) {
    int i = blockIdx.x * blockDim.x + threadIdx.x;
    if (i < n) p[i] = 0.0f;
}

// ------------------------- weight transpose + tf32 round ---------------------
__global__ void convt_kernel(const float* __restrict__ in, float* __restrict__ out,
                             int K, int N, int Kpad) {
    __shared__ float tile[32][33];
    int kb = blockIdx.x * 32, nb = blockIdx.y * 32;
    int tx = threadIdx.x, ty = threadIdx.y;
    #pragma unroll
    for (int i = ty; i < 32; i += 8) {
        int k = kb + i, n = nb + tx;
        tile[i][tx] = (k < K && n < N) ? in[(size_t)k * N + n] : 0.0f;
    }
    __syncthreads();
    #pragma unroll
    for (int i = ty; i < 32; i += 8) {
        int n = nb + i, k = kb + tx;
        if (n < N && k < Kpad) out[(size_t)n * Kpad + k] = to_tf32(tile[tx][i]);
    }
}

// ------------------------- tf32 tensor-core GEMM with fused epilogue ---------
#define TBM 128
#define TBN 128
#define TBK 16
#define SA  20
#define SB  20

__global__ __launch_bounds__(256, 2)
void gemm_tc_kernel(const float* __restrict__ A,
                    const float* __restrict__ Bt,
                    const float* __restrict__ bias,
                    const float* __restrict__ rowscale,
                    const float* __restrict__ addsrc,
                    float* __restrict__ C,
                    int M, int N, int K, int Kpad, int do_ssp) {
    __shared__ __align__(16) float As[2][TBM * SA];
    __shared__ __align__(16) float Bs[2][TBN * SB];

    const int bm = blockIdx.y * TBM;
    const int bn = blockIdx.x * TBN;
    const int tid  = threadIdx.x;
    const int lane = tid & 31;
    const int warp = tid >> 5;
    const int wm0 = (warp >> 2) * 64;
    const int wn0 = (warp & 3) * 32;
    const int gid = lane >> 2;
    const int lk  = lane & 3;

    const int srow = tid >> 1;
    const int scol = (tid & 1) * 8;
    const bool a_vec_ok = ((K & 3) == 0);

    float acc[4][4][4];
    #pragma unroll
    for (int i = 0; i < 4; i++)
        #pragma unroll
        for (int j = 0; j < 4; j++)
            #pragma unroll
            for (int c = 0; c < 4; c++) acc[i][j][c] = 0.0f;

    const int nsteps = Kpad / TBK;
    float aS[8], bS[8];

    auto loadA = [&](int k0) {
        int gm = bm + srow;
        int kb = k0 + scol;
        if (a_vec_ok && gm < M && kb + 7 < K) {
            const float4* ap = (const float4*)(A + (size_t)gm * K + kb);
            float4 v0 = ap[0], v1 = ap[1];
            aS[0] = v0.x; aS[1] = v0.y; aS[2] = v0.z; aS[3] = v0.w;
            aS[4] = v1.x; aS[5] = v1.y; aS[6] = v1.z; aS[7] = v1.w;
        } else {
            const float* ap = A + (size_t)gm * K;
            #pragma unroll
            for (int i = 0; i < 8; i++)
                aS[i] = (gm < M && kb + i < K) ? ap[kb + i] : 0.0f;
        }
        #pragma unroll
        for (int i = 0; i < 8; i++) aS[i] = to_tf32(aS[i]);
    };
    auto loadB = [&](int k0) {
        int gn = bn + srow;
        if (gn < N) {
            const float4* bp = (const float4*)(Bt + (size_t)gn * Kpad + k0 + scol);
            float4 v0 = bp[0], v1 = bp[1];
            bS[0] = v0.x; bS[1] = v0.y; bS[2] = v0.z; bS[3] = v0.w;
            bS[4] = v1.x; bS[5] = v1.y; bS[6] = v1.z; bS[7] = v1.w;
        } else {
            #pragma unroll
            for (int i = 0; i < 8; i++) bS[i] = 0.0f;
        }
    };
    auto stsA = [&](int buf) {
        float* p = &As[buf][srow * SA + scol];
        *(float4*)p       = make_float4(aS[0], aS[1], aS[2], aS[3]);
        *(float4*)(p + 4) = make_float4(aS[4], aS[5], aS[6], aS[7]);
    };
    auto stsB = [&](int buf) {
        float* p = &Bs[buf][srow * SB + scol];
        *(float4*)p       = make_float4(bS[0], bS[1], bS[2], bS[3]);
        *(float4*)(p + 4) = make_float4(bS[4], bS[5], bS[6], bS[7]);
    };

    loadA(0); loadB(0);
    stsA(0); stsB(0);
    __syncthreads();

    for (int s = 0; s < nsteps; s++) {
        if (s + 1 < nsteps) { loadA((s + 1) * TBK); loadB((s + 1) * TBK); }

        const float* as = As[s & 1];
        const float* bs = Bs[s & 1];
        #pragma unroll
        for (int ks = 0; ks < 2; ks++) {
            int kof = ks * 8 + lk;
            unsigned int af[4][4], bf[4][2];
            #pragma unroll
            for (int mt = 0; mt < 4; mt++) {
                int r = wm0 + mt * 16 + gid;
                af[mt][0] = __float_as_uint(as[r * SA + kof]);
                af[mt][1] = __float_as_uint(as[(r + 8) * SA + kof]);
                af[mt][2] = __float_as_uint(as[r * SA + kof + 4]);
                af[mt][3] = __float_as_uint(as[(r + 8) * SA + kof + 4]);
            }
            #pragma unroll
            for (int nt = 0; nt < 4; nt++) {
                int c = wn0 + nt * 8 + gid;
                bf[nt][0] = __float_as_uint(bs[c * SB + kof]);
                bf[nt][1] = __float_as_uint(bs[c * SB + kof + 4]);
            }
            #pragma unroll
            for (int mt = 0; mt < 4; mt++)
                #pragma unroll
                for (int nt = 0; nt < 4; nt++) {
                    asm volatile(
                        "mma.sync.aligned.m16n8k8.row.col.f32.tf32.tf32.f32 "
                        "{%0,%1,%2,%3}, {%4,%5,%6,%7}, {%8,%9}, {%0,%1,%2,%3};"
                        : "+f"(acc[mt][nt][0]), "+f"(acc[mt][nt][1]),
                          "+f"(acc[mt][nt][2]), "+f"(acc[mt][nt][3])
                        : "r"(af[mt][0]), "r"(af[mt][1]), "r"(af[mt][2]), "r"(af[mt][3]),
                          "r"(bf[nt][0]), "r"(bf[nt][1]));
                }
        }
        if (s + 1 < nsteps) {
            __syncthreads();
            stsA((s + 1) & 1); stsB((s + 1) & 1);
            __syncthreads();
        }
    }

    #pragma unroll
    for (int mt = 0; mt < 4; mt++) {
        #pragma unroll
        for (int rr = 0; rr < 2; rr++) {
            int gm = bm + wm0 + mt * 16 + gid + rr * 8;
            if (gm >= M) continue;
            float rs = rowscale ? rowscale[gm] : 1.0f;
            #pragma unroll
            for (int nt = 0; nt < 4; nt++) {
                #pragma unroll
                for (int cc = 0; cc < 2; cc++) {
                    int gn = bn + wn0 + nt * 8 + lk * 2 + cc;
                    if (gn >= N) continue;
                    float v = acc[mt][nt][rr * 2 + cc];
                    if (bias) v += bias[gn];
                    if (do_ssp) v = sspf(v);
                    if (rowscale) v *= rs;
                    if (addsrc) v += addsrc[(size_t)gm * N + gn];
                    C[(size_t)gm * N + gn] = v;
                }
            }
        }
    }
}

// ------------------------- CFConv scatter with table interpolation -----------
// agg[dst[e], :] += xjp[src[e], :] * lerp(Wtab[i0[e]], Wtab[i0[e]+1], fr[e])
__global__ void scatter_kernel(const int* __restrict__ src,
                               const int* __restrict__ dst) {
    int i = blockIdx.x * blockDim.x + threadIdx.x;
    if (i >= NEDGE * HID4) return;
    int e = i / HID4;
    int j = i - e * HID4;
    int s = src[e], d = dst[e];
    int i0 = g_ei0[e];
    float f = g_efr[e];
    const float4* tp = (const float4*)g_Wtab;
    const float4* xp = (const float4*)g_xjp;
    float4 w0 = tp[(size_t)i0 * HID4 + j];
    float4 w1 = tp[(size_t)(i0 + 1) * HID4 + j];
    float4 x  = xp[(size_t)s * HID4 + j];
    float4 v;
    v.x = x.x * fmaf(f, w1.x - w0.x, w0.x);
    v.y = x.y * fmaf(f, w1.y - w0.y, w0.y);
    v.z = x.z * fmaf(f, w1.z - w0.z, w0.z);
    v.w = x.w * fmaf(f, w1.w - w0.w, w0.w);
    float* a = g_agg + ((size_t)d * HID + j * 4);
    asm volatile("red.global.add.v4.f32 [%0], {%1,%2,%3,%4};"
                 :: "l"(a), "f"(v.x), "f"(v.y), "f"(v.z), "f"(v.w) : "memory");
}

// ------------------------- segment-mean pool ---------------------------------
__global__ void pool_kernel(const int* __restrict__ batch) {
    int b = blockIdx.x;
    int t = threadIdx.x;
    int lo = 0, hi = NATOMS;
    while (lo < hi) { int mid = (lo + hi) >> 1; if (batch[mid] < b) lo = mid + 1; else hi = mid; }
    int start = lo;
    lo = start; hi = NATOMS;
    while (lo < hi) { int mid = (lo + hi) >> 1; if (batch[mid] <= b) lo = mid + 1; else hi = mid; }
    int end = lo;
    int cnt = end - start;
    float inv = cnt > 0 ? 1.0f / (float)cnt : 0.0f;
    if (t < HID) {
        float s = 0.0f;
        for (int n = start; n < end; n++) s += g_h[n * HID + t];
        g_pool[b * HID + t] = s * inv;
    }
}

// ------------------------- host orchestration --------------------------------
static inline void launch_gemm(const float* A, const float* Bt, const float* bias,
                               const float* rowscale, const float* addsrc,
                               float* C, int M, int N, int K, int Kpad, int do_ssp) {
    dim3 grid((N + TBN - 1) / TBN, (M + TBM - 1) / TBM);
    gemm_tc_kernel<<<grid, 256>>>(A, Bt, bias, rowscale, addsrc, C, M, N, K, Kpad, do_ssp);
}

static inline void launch_convt(const float* in, float* out, int K, int N, int Kpad) {
    dim3 grid((Kpad + 31) / 32, (N + 31) / 32);
    convt_kernel<<<grid, dim3(32, 8)>>>(in, out, K, N, Kpad);
}

extern "C" void kernel_launch(void* const* d_in, const int* in_sizes, int n_in,
                              void* d_out, int out_size) {
    const int*   z     = (const int*)  d_in[0];
    const float* pos   = (const float*)d_in[1];
    const int*   batch = (const int*)  d_in[2];
    const int*   ei    = (const int*)  d_in[3];
    const float* emb   = (const float*)d_in[4];
    const float* w1    = (const float*)d_in[5];
    const float* b1    = (const float*)d_in[6];
    const float* w2    = (const float*)d_in[7];
    const float* b2    = (const float*)d_in[8];
    const float* l1w   = (const float*)d_in[9];
    const float* l2w   = (const float*)d_in[10];
    const float* l2b   = (const float*)d_in[11];
    const float* ilw   = (const float*)d_in[12];
    const float* ilb   = (const float*)d_in[13];
    const float* pw    = (const float*)d_in[14];
    const float* pb    = (const float*)d_in[15];
    (void)in_sizes; (void)n_in; (void)out_size;

    const int* src = ei;
    const int* dst = ei + NEDGE;

    float *prbftab, *pCtab, *pF1tab, *pWtab, *ph, *pxjp, *pagg, *pt1, *ppool;
    float *pw1t, *pw2t, *pl1t, *pl2t, *pilt, *ppwt;
    cudaGetSymbolAddress((void**)&prbftab, g_rbftab);
    cudaGetSymbolAddress((void**)&pCtab,  g_Ctab);
    cudaGetSymbolAddress((void**)&pF1tab, g_F1tab);
    cudaGetSymbolAddress((void**)&pWtab,  g_Wtab);
    cudaGetSymbolAddress((void**)&ph,     g_h);
    cudaGetSymbolAddress((void**)&pxjp,   g_xjp);
    cudaGetSymbolAddress((void**)&pagg,   g_agg);
    cudaGetSymbolAddress((void**)&pt1,    g_t1);
    cudaGetSymbolAddress((void**)&ppool,  g_pool);
    cudaGetSymbolAddress((void**)&pw1t,   g_w1t);
    cudaGetSymbolAddress((void**)&pw2t,   g_w2t);
    cudaGetSymbolAddress((void**)&pl1t,   g_l1t);
    cudaGetSymbolAddress((void**)&pl2t,   g_l2t);
    cudaGetSymbolAddress((void**)&pilt,   g_ilt);
    cudaGetSymbolAddress((void**)&ppwt,   g_pwt);

    // weight transpose + tf32 rounding
    for (int k = 0; k < NL; k++) {
        launch_convt(w1  + (size_t)k * NG  * HID, pw1t + (size_t)k * HID * KP_G, NG,  HID, KP_G);
        launch_convt(w2  + (size_t)k * HID * HID, pw2t + (size_t)k * HID * KP_H, HID, HID, KP_H);
        launch_convt(l1w + (size_t)k * HID * HID, pl1t + (size_t)k * HID * KP_H, HID, HID, KP_H);
        launch_convt(l2w + (size_t)k * HID * HID, pl2t + (size_t)k * HID * KP_H, HID, HID, KP_H);
        launch_convt(ilw + (size_t)k * HID * HID, pilt + (size_t)k * HID * KP_H, HID, HID, KP_H);
    }
    launch_convt(pw, ppwt, HID, HID, KP_H);

    // edge table coords + rbf table + embedding init
    edge_geom_kernel<<<(NEDGE + 255) / 256, 256>>>(pos, src, dst);
    rbftab_kernel<<<(TAB * KP_G + 255) / 256, 256>>>();
    emb_kernel<<<(NATOMS * HID + 255) / 256, 256>>>(z, emb);

    for (int k = 0; k < NL; k++) {
        const float* b1k  = b1  + (size_t)k * HID;
        const float* b2k  = b2  + (size_t)k * HID;
        const float* l2bk = l2b + (size_t)k * HID;
        const float* ilbk = ilb + (size_t)k * HID;
        const float* w1tk = pw1t + (size_t)k * HID * KP_G;
        const float* w2tk = pw2t + (size_t)k * HID * KP_H;
        const float* l1tk = pl1t + (size_t)k * HID * KP_H;
        const float* l2tk = pl2t + (size_t)k * HID * KP_H;
        const float* iltk = pilt + (size_t)k * HID * KP_H;

        // F1tab = ssp(rbftab @ w1 + b1)                 [TAB,H] (rbftab pre-padded to 64 cols)
        launch_gemm(prbftab, w1tk, b1k, nullptr, nullptr, pF1tab, TAB, HID, KP_G, KP_G, 1);
        // Wtab = (F1tab @ w2 + b2) * Ctab               [TAB,H]
        launch_gemm(pF1tab, w2tk, b2k, pCtab, nullptr, pWtab, TAB, HID, HID, KP_H, 0);
        // xjp = h @ lin1                                [N,H]
        launch_gemm(ph, l1tk, nullptr, nullptr, nullptr, pxjp, NATOMS, HID, HID, KP_H, 0);
        // agg = scatter_add(xjp[src] * W(d) -> dst)     [N,H]
        zero_kernel<<<(NATOMS * HID + 255) / 256, 256>>>(pagg, NATOMS * HID);
        scatter_kernel<<<(NEDGE * HID4 + 255) / 256, 256>>>(src, dst);
        // t1 = ssp(agg @ lin2 + lin2_b)                 [N,H]
        launch_gemm(pagg, l2tk, l2bk, nullptr, nullptr, pt1, NATOMS, HID, HID, KP_H, 1);
        // h = h + t1 @ int_lin + int_b                  [N,H]
        launch_gemm(pt1, iltk, ilbk, nullptr, ph, ph, NATOMS, HID, HID, KP_H, 0);
    }

    // segment-mean pool, final projection
    pool_kernel<<<BG, 640>>>(batch);
    launch_gemm(ppool, ppwt, pb, nullptr, nullptr, (float*)d_out, BG, HID, HID, KP_H, 0);
}

// round 12
// speedup vs baseline: 9.3233x; 1.3257x over previous
#include <cuda_runtime.h>
#include <cuda_bf16.h>
#include <stdint.h>
#include <math.h>

#define NATOMS 10000
#define NEDGE  64000
#define BG     128
#define HID    600
#define NG     50
#define NL     6
#define HID4   150     // HID/4
#define KP_H   608     // HID padded to 16
#define KP_G   64      // NG padded to 16
#define TAB    4096    // W(d) table resolution
#define DMAX   8.6603f // > sqrt(75) = max possible distance
#define TDELTA (DMAX / (TAB - 1))

// ------------------------- scratch (static device globals) -------------------
__device__ int   g_ei0[NEDGE];          // table index per edge
__device__ float g_efr[NEDGE];          // interpolation fraction per edge
__device__ float g_rbftab[TAB * KP_G];  // rbf at table points (padded cols, tf32)
__device__ float g_Ctab  [TAB];         // cosine cutoff at table points
__device__ float g_F1tab [TAB * HID];
__device__ float g_Wtab  [TAB * HID];
__device__ float g_h  [NATOMS * HID];
__device__ float g_xjp[NATOMS * HID];
__device__ float g_agg[NATOMS * HID];
__device__ float g_t1 [NATOMS * HID];
__device__ float g_pool[BG * HID];

// tf32-rounded transposed weights (stored as f32): layout [N][Kpad]
__device__ float g_w1t [NL * HID * KP_G];
__device__ float g_w2t [NL * HID * KP_H];
__device__ float g_l1t [NL * HID * KP_H];
__device__ float g_l2t [NL * HID * KP_H];
__device__ float g_ilt [NL * HID * KP_H];
__device__ float g_pwt [HID * KP_H];

// ------------------------- helpers ------------------------------------------
__device__ __forceinline__ float sspf(float x) {
    float ax = fabsf(x);
    return fmaxf(x, 0.0f) + log1pf(expf(-ax)) - 0.69314718055994531f;
}

__device__ __forceinline__ float to_tf32(float x) {
    float r;
    asm("cvt.rna.tf32.f32 %0, %1;" : "=f"(r) : "f"(x));
    return r;
}

// ------------------------- edge geometry -> table coords ---------------------
__global__ void edge_geom_kernel(const float* __restrict__ pos,
                                 const int* __restrict__ src,
                                 const int* __restrict__ dst) {
    int e = blockIdx.x * blockDim.x + threadIdx.x;
    if (e >= NEDGE) return;
    int s = src[e], t = dst[e];
    float dx = pos[s*3+0] - pos[t*3+0];
    float dy = pos[s*3+1] - pos[t*3+1];
    float dz = pos[s*3+2] - pos[t*3+2];
    float d = sqrtf(dx*dx + dy*dy + dz*dz + 1e-12f);
    float tt = d * (1.0f / TDELTA);
    int i0 = (int)tt;
    if (i0 > TAB - 2) i0 = TAB - 2;
    g_ei0[e] = i0;
    g_efr[e] = tt - (float)i0;
}

// ------------------------- rbf + cutoff table (tf32-rounded) -----------------
__global__ void rbftab_kernel() {
    int i = blockIdx.x * blockDim.x + threadIdx.x;
    if (i >= TAB * KP_G) return;
    int r = i / KP_G;
    int g = i - r * KP_G;
    float d = (float)r * TDELTA;
    float v = 0.0f;
    if (g < NG) {
        float off = (float)g * (10.0f / 49.0f);
        float dd  = d - off;
        v = expf(-12.005f * dd * dd);
    }
    g_rbftab[i] = to_tf32(v);
    if (g == 0)
        g_Ctab[r] = 0.5f * (cosf(d * 0.31415926535897931f) + 1.0f);
}

__global__ void emb_kernel(const int* __restrict__ z, const float* __restrict__ emb) {
    int i = blockIdx.x * blockDim.x + threadIdx.x;
    if (i >= NATOMS * HID) return;
    int n = i / HID;
    int j = i - n * HID;
    g_h[i] = to_tf32(emb[z[n] * HID + j]);
}

__global__ void zero_kernel(float* __restrict__ p, int n) {
    int i = blockIdx.x * blockDim.x + threadIdx.x;
    if (i < n) p[i] = 0.0f;
}

// round a buffer in place to tf32 (float4 vectorized)
__global__ void round4_kernel(float* __restrict__ p, int n4) {
    int i = blockIdx.x * blockDim.x + threadIdx.x;
    if (i >= n4) return;
    float4 v = ((float4*)p)[i];
    v.x = to_tf32(v.x); v.y = to_tf32(v.y);
    v.z = to_tf32(v.z); v.w = to_tf32(v.w);
    ((float4*)p)[i] = v;
}

// ------------------------- weight transpose + tf32 round (batched) -----------
// out[z][n*Kpad + k] = tf32(in[z][k*N + n]), zero for k >= K; batch via grid.z
__global__ void convt_kernel(const float* __restrict__ in, float* __restrict__ out,
                             int K, int N, int Kpad,
                             long in_stride, long out_stride) {
    in  += (size_t)blockIdx.z * in_stride;
    out += (size_t)blockIdx.z * out_stride;
    __shared__ float tile[32][33];
    int kb = blockIdx.x * 32, nb = blockIdx.y * 32;
    int tx = threadIdx.x, ty = threadIdx.y;
    #pragma unroll
    for (int i = ty; i < 32; i += 8) {
        int k = kb + i, n = nb + tx;
        tile[i][tx] = (k < K && n < N) ? in[(size_t)k * N + n] : 0.0f;
    }
    __syncthreads();
    #pragma unroll
    for (int i = ty; i < 32; i += 8) {
        int n = nb + i, k = kb + tx;
        if (n < N && k < Kpad) out[(size_t)n * Kpad + k] = to_tf32(tile[tx][i]);
    }
}

// ------------------------- tf32 tensor-core GEMM (cp.async pipeline) ---------
// C[M,N] = ep( A[M,K](pre-rounded tf32 f32) @ Bt[N,Kpad](tf32 f32, transposed) )
// CTA 128x128x16, 8 warps (2x4), warp tile 64x32, mma.m16n8k8, fp32 acc.
// Requirements: A rows 16B-aligned (K % 4 == 0), Kpad % 16 == 0.
#define TBM 128
#define TBN 128
#define TBK 16
#define SA  20
#define SB  20

__global__ __launch_bounds__(256, 2)
void gemm_tc_kernel(const float* __restrict__ A,
                    const float* __restrict__ Bt,
                    const float* __restrict__ bias,
                    const float* __restrict__ rowscale,
                    const float* __restrict__ addsrc,
                    float* __restrict__ C,
                    int M, int N, int K, int Kpad, int do_ssp, int do_round) {
    __shared__ __align__(16) float As[2][TBM * SA];
    __shared__ __align__(16) float Bs[2][TBN * SB];

    const int bm = blockIdx.y * TBM;
    const int bn = blockIdx.x * TBN;
    const int tid  = threadIdx.x;
    const int lane = tid & 31;
    const int warp = tid >> 5;
    const int wm0 = (warp >> 2) * 64;
    const int wn0 = (warp & 3) * 32;
    const int gid = lane >> 2;
    const int lk  = lane & 3;

    // staging mapping: row = tid>>1 (0..127), col half = (tid&1)*8
    const int srow = tid >> 1;
    const int scol = (tid & 1) * 8;

    const uint32_t sAbase = (uint32_t)__cvta_generic_to_shared(&As[0][0]);
    const uint32_t sBbase = (uint32_t)__cvta_generic_to_shared(&Bs[0][0]);

    float acc[4][4][4] = {};

    const int nsteps = Kpad / TBK;

    auto stage = [&](int k0, int buf) {
        // ---- A tile ----
        int gm = bm + srow;
        uint32_t da = sAbase + (uint32_t)((buf * TBM * SA + srow * SA + scol) * 4);
        const float* arow = A + (size_t)(gm < M ? gm : 0) * K;
        #pragma unroll
        for (int h2 = 0; h2 < 2; h2++) {
            int gk = k0 + scol + h2 * 4;
            int nb = (gm < M) ? (K - gk) * 4 : 0;
            nb = nb < 0 ? 0 : (nb > 16 ? 16 : nb);
            const float* gp = arow + (nb > 0 ? gk : 0);
            asm volatile("cp.async.cg.shared.global [%0], [%1], 16, %2;"
                         :: "r"(da + h2 * 16), "l"(gp), "r"(nb));
        }
        // ---- B tile ----
        int gn = bn + srow;
        uint32_t db = sBbase + (uint32_t)((buf * TBN * SB + srow * SB + scol) * 4);
        const float* brow = Bt + (size_t)(gn < N ? gn : 0) * Kpad + k0 + scol;
        int nbB = (gn < N) ? 16 : 0;
        #pragma unroll
        for (int h2 = 0; h2 < 2; h2++) {
            asm volatile("cp.async.cg.shared.global [%0], [%1], 16, %2;"
                         :: "r"(db + h2 * 16), "l"(brow + h2 * 4), "r"(nbB));
        }
        asm volatile("cp.async.commit_group;" ::: "memory");
    };

    stage(0, 0);
    asm volatile("cp.async.wait_group 0;" ::: "memory");
    __syncthreads();

    for (int s = 0; s < nsteps; s++) {
        if (s + 1 < nsteps) stage((s + 1) * TBK, (s + 1) & 1);

        const float* as = As[s & 1];
        const float* bs = Bs[s & 1];
        #pragma unroll
        for (int ks = 0; ks < 2; ks++) {
            int kof = ks * 8 + lk;
            unsigned int af[4][4], bf[4][2];
            #pragma unroll
            for (int mt = 0; mt < 4; mt++) {
                int r = wm0 + mt * 16 + gid;
                af[mt][0] = __float_as_uint(as[r * SA + kof]);
                af[mt][1] = __float_as_uint(as[(r + 8) * SA + kof]);
                af[mt][2] = __float_as_uint(as[r * SA + kof + 4]);
                af[mt][3] = __float_as_uint(as[(r + 8) * SA + kof + 4]);
            }
            #pragma unroll
            for (int nt = 0; nt < 4; nt++) {
                int c = wn0 + nt * 8 + gid;
                bf[nt][0] = __float_as_uint(bs[c * SB + kof]);
                bf[nt][1] = __float_as_uint(bs[c * SB + kof + 4]);
            }
            #pragma unroll
            for (int mt = 0; mt < 4; mt++)
                #pragma unroll
                for (int nt = 0; nt < 4; nt++) {
                    asm volatile(
                        "mma.sync.aligned.m16n8k8.row.col.f32.tf32.tf32.f32 "
                        "{%0,%1,%2,%3}, {%4,%5,%6,%7}, {%8,%9}, {%0,%1,%2,%3};"
                        : "+f"(acc[mt][nt][0]), "+f"(acc[mt][nt][1]),
                          "+f"(acc[mt][nt][2]), "+f"(acc[mt][nt][3])
                        : "r"(af[mt][0]), "r"(af[mt][1]), "r"(af[mt][2]), "r"(af[mt][3]),
                          "r"(bf[nt][0]), "r"(bf[nt][1]));
                }
        }
        if (s + 1 < nsteps)
            asm volatile("cp.async.wait_group 0;" ::: "memory");
        __syncthreads();
    }

    // ---- epilogue ----  (C frag: row = gid (+8), col = lk*2 (+1))
    #pragma unroll
    for (int mt = 0; mt < 4; mt++) {
        #pragma unroll
        for (int rr = 0; rr < 2; rr++) {
            int gm = bm + wm0 + mt * 16 + gid + rr * 8;
            if (gm >= M) continue;
            float rs = rowscale ? rowscale[gm] : 1.0f;
            #pragma unroll
            for (int nt = 0; nt < 4; nt++) {
                #pragma unroll
                for (int cc = 0; cc < 2; cc++) {
                    int gn = bn + wn0 + nt * 8 + lk * 2 + cc;
                    if (gn >= N) continue;
                    float v = acc[mt][nt][rr * 2 + cc];
                    if (bias) v += bias[gn];
                    if (do_ssp) v = sspf(v);
                    if (rowscale) v *= rs;
                    if (addsrc) v += addsrc[(size_t)gm * N + gn];
                    if (do_round) v = to_tf32(v);
                    C[(size_t)gm * N + gn] = v;
                }
            }
        }
    }
}

// ------------------------- CFConv scatter with table interpolation -----------
__global__ void scatter_kernel(const int* __restrict__ src,
                               const int* __restrict__ dst) {
    int i = blockIdx.x * blockDim.x + threadIdx.x;
    if (i >= NEDGE * HID4) return;
    int e = i / HID4;
    int j = i - e * HID4;
    int s = src[e], d = dst[e];
    int i0 = g_ei0[e];
    float f = g_efr[e];
    const float4* tp = (const float4*)g_Wtab;
    const float4* xp = (const float4*)g_xjp;
    float4 w0 = tp[(size_t)i0 * HID4 + j];
    float4 w1 = tp[(size_t)(i0 + 1) * HID4 + j];
    float4 x  = xp[(size_t)s * HID4 + j];
    float4 v;
    v.x = x.x * fmaf(f, w1.x - w0.x, w0.x);
    v.y = x.y * fmaf(f, w1.y - w0.y, w0.y);
    v.z = x.z * fmaf(f, w1.z - w0.z, w0.z);
    v.w = x.w * fmaf(f, w1.w - w0.w, w0.w);
    float* a = g_agg + ((size_t)d * HID + j * 4);
    asm volatile("red.global.add.v4.f32 [%0], {%1,%2,%3,%4};"
                 :: "l"(a), "f"(v.x), "f"(v.y), "f"(v.z), "f"(v.w) : "memory");
}

// ------------------------- segment-mean pool (rounded for final GEMM) --------
__global__ void pool_kernel(const int* __restrict__ batch) {
    int b = blockIdx.x;
    int t = threadIdx.x;
    int lo = 0, hi = NATOMS;
    while (lo < hi) { int mid = (lo + hi) >> 1; if (batch[mid] < b) lo = mid + 1; else hi = mid; }
    int start = lo;
    lo = start; hi = NATOMS;
    while (lo < hi) { int mid = (lo + hi) >> 1; if (batch[mid] <= b) lo = mid + 1; else hi = mid; }
    int end = lo;
    int cnt = end - start;
    float inv = cnt > 0 ? 1.0f / (float)cnt : 0.0f;
    if (t < HID) {
        float s = 0.0f;
        for (int n = start; n < end; n++) s += g_h[n * HID + t];
        g_pool[b * HID + t] = to_tf32(s * inv);
    }
}

// ------------------------- host orchestration --------------------------------
static inline void launch_gemm(const float* A, const float* Bt, const float* bias,
                               const float* rowscale, const float* addsrc,
                               float* C, int M, int N, int K, int Kpad,
                               int do_ssp, int do_round) {
    dim3 grid((N + TBN - 1) / TBN, (M + TBM - 1) / TBM);
    gemm_tc_kernel<<<grid, 256>>>(A, Bt, bias, rowscale, addsrc, C,
                                  M, N, K, Kpad, do_ssp, do_round);
}

static inline void launch_convt(const float* in, float* out, int K, int N, int Kpad,
                                long in_stride, long out_stride, int nbatch) {
    dim3 grid((Kpad + 31) / 32, (N + 31) / 32, nbatch);
    convt_kernel<<<grid, dim3(32, 8)>>>(in, out, K, N, Kpad, in_stride, out_stride);
}

extern "C" void kernel_launch(void* const* d_in, const int* in_sizes, int n_in,
                              void* d_out, int out_size) {
    const int*   z     = (const int*)  d_in[0];
    const float* pos   = (const float*)d_in[1];
    const int*   batch = (const int*)  d_in[2];
    const int*   ei    = (const int*)  d_in[3];
    const float* emb   = (const float*)d_in[4];
    const float* w1    = (const float*)d_in[5];
    const float* b1    = (const float*)d_in[6];
    const float* w2    = (const float*)d_in[7];
    const float* b2    = (const float*)d_in[8];
    const float* l1w   = (const float*)d_in[9];
    const float* l2w   = (const float*)d_in[10];
    const float* l2b   = (const float*)d_in[11];
    const float* ilw   = (const float*)d_in[12];
    const float* ilb   = (const float*)d_in[13];
    const float* pw    = (const float*)d_in[14];
    const float* pb    = (const float*)d_in[15];
    (void)in_sizes; (void)n_in; (void)out_size;

    const int* src = ei;
    const int* dst = ei + NEDGE;

    float *prbftab, *pCtab, *pF1tab, *pWtab, *ph, *pxjp, *pagg, *pt1, *ppool;
    float *pw1t, *pw2t, *pl1t, *pl2t, *pilt, *ppwt;
    cudaGetSymbolAddress((void**)&prbftab, g_rbftab);
    cudaGetSymbolAddress((void**)&pCtab,  g_Ctab);
    cudaGetSymbolAddress((void**)&pF1tab, g_F1tab);
    cudaGetSymbolAddress((void**)&pWtab,  g_Wtab);
    cudaGetSymbolAddress((void**)&ph,     g_h);
    cudaGetSymbolAddress((void**)&pxjp,   g_xjp);
    cudaGetSymbolAddress((void**)&pagg,   g_agg);
    cudaGetSymbolAddress((void**)&pt1,    g_t1);
    cudaGetSymbolAddress((void**)&ppool,  g_pool);
    cudaGetSymbolAddress((void**)&pw1t,   g_w1t);
    cudaGetSymbolAddress((void**)&pw2t,   g_w2t);
    cudaGetSymbolAddress((void**)&pl1t,   g_l1t);
    cudaGetSymbolAddress((void**)&pl2t,   g_l2t);
    cudaGetSymbolAddress((void**)&pilt,   g_ilt);
    cudaGetSymbolAddress((void**)&ppwt,   g_pwt);

    // weight transpose + tf32 rounding (batched over layers)
    launch_convt(w1,  pw1t, NG,  HID, KP_G, (long)NG  * HID, (long)HID * KP_G, NL);
    launch_convt(w2,  pw2t, HID, HID, KP_H, (long)HID * HID, (long)HID * KP_H, NL);
    launch_convt(l1w, pl1t, HID, HID, KP_H, (long)HID * HID, (long)HID * KP_H, NL);
    launch_convt(l2w, pl2t, HID, HID, KP_H, (long)HID * HID, (long)HID * KP_H, NL);
    launch_convt(ilw, pilt, HID, HID, KP_H, (long)HID * HID, (long)HID * KP_H, NL);
    launch_convt(pw,  ppwt, HID, HID, KP_H, 0, 0, 1);

    // edge table coords + rbf table + embedding init
    edge_geom_kernel<<<(NEDGE + 255) / 256, 256>>>(pos, src, dst);
    rbftab_kernel<<<(TAB * KP_G + 255) / 256, 256>>>();
    emb_kernel<<<(NATOMS * HID + 255) / 256, 256>>>(z, emb);

    for (int k = 0; k < NL; k++) {
        const float* b1k  = b1  + (size_t)k * HID;
        const float* b2k  = b2  + (size_t)k * HID;
        const float* l2bk = l2b + (size_t)k * HID;
        const float* ilbk = ilb + (size_t)k * HID;
        const float* w1tk = pw1t + (size_t)k * HID * KP_G;
        const float* w2tk = pw2t + (size_t)k * HID * KP_H;
        const float* l1tk = pl1t + (size_t)k * HID * KP_H;
        const float* l2tk = pl2t + (size_t)k * HID * KP_H;
        const float* iltk = pilt + (size_t)k * HID * KP_H;

        // F1tab = ssp(rbftab @ w1 + b1), tf32-rounded        [TAB,H]
        launch_gemm(prbftab, w1tk, b1k, nullptr, nullptr, pF1tab, TAB, HID, KP_G, KP_G, 1, 1);
        // Wtab = (F1tab @ w2 + b2) * Ctab  (full f32)        [TAB,H]
        launch_gemm(pF1tab, w2tk, b2k, pCtab, nullptr, pWtab, TAB, HID, HID, KP_H, 0, 0);
        // xjp = h @ lin1  (full f32, feeds scatter)          [N,H]
        launch_gemm(ph, l1tk, nullptr, nullptr, nullptr, pxjp, NATOMS, HID, HID, KP_H, 0, 0);
        // agg = scatter_add(xjp[src] * W(d) -> dst)          [N,H]
        zero_kernel<<<(NATOMS * HID + 255) / 256, 256>>>(pagg, NATOMS * HID);
        scatter_kernel<<<(NEDGE * HID4 + 255) / 256, 256>>>(src, dst);
        round4_kernel<<<(NATOMS * HID4 + 255) / 256, 256>>>(pagg, NATOMS * HID4);
        // t1 = ssp(agg @ lin2 + lin2_b), tf32-rounded        [N,H]
        launch_gemm(pagg, l2tk, l2bk, nullptr, nullptr, pt1, NATOMS, HID, HID, KP_H, 1, 1);
        // h = h + t1 @ int_lin + int_b, tf32-rounded         [N,H]
        launch_gemm(pt1, iltk, ilbk, nullptr, ph, ph, NATOMS, HID, HID, KP_H, 0, 1);
    }

    // segment-mean pool (rounded), final projection (full precision out)
    pool_kernel<<<BG, 640>>>(batch);
    launch_gemm(ppool, ppwt, pb, nullptr, nullptr, (float*)d_out, BG, HID, HID, KP_H, 0, 0);
}